// round 15
// baseline (speedup 1.0000x reference)
#include <cuda_runtime.h>
#include <math.h>
#include <stdint.h>

#define D 512
#define C 17
#define RMAX 131072
#define NBA 4096
#define NLOW 256
#define CANDCAP 32768
#define TIECAP 512
#define LCAP 4096
#define CH2 96

// ---------------- device scratch (static; zero-init at module load) -------
__device__ uint2    g_keys[RMAX];        // {entropy bits, class}
__device__ unsigned g_histA[C * NBA];    // re-zeroed by k_gemm2 each run
__device__ unsigned g_lowhist[C * NLOW]; // re-zeroed by k_gemm2 each run
__device__ unsigned g_prefA[C];
__device__ int      g_kleft[C];
__device__ int      g_cnt[C];
__device__ int      g_candcnt[C];
__device__ int      g_cand[C][CANDCAP];
__device__ int      g_list[(size_t)C * LCAP];
__device__ float    g_Wc[C * D];         // zeroed in scanA tail, REDG in k_sum
__device__ float    g_rn[C];
__device__ unsigned g_done1;             // k_logits tail counter (reset by k_gemm2)
__device__ unsigned g_done2;             // k_compact tail counter (reset by k_gemm2)
__device__ unsigned g_done3;             // k_sum counter (self-reset)

// ---- kernel 1: logits (2 rows/warp) + keys/hist + tail scanA --------------
__global__ void k_logits(const float* __restrict__ feat,
                         const float* __restrict__ w,
                         const float* __restrict__ bias,
                         const float* __restrict__ entbank,
                         const int*   __restrict__ labels,
                         int B, int N, const int* __restrict__ kptr) {
    int tid = blockIdx.x * blockDim.x + threadIdx.x;
    int nth = gridDim.x * blockDim.x;
    for (int i = tid; i < N; i += nth) {
        unsigned bits = __float_as_uint(entbank[i]);  // entropies >= 0: monotone
        int c = labels[i];
        g_keys[i] = make_uint2(bits, (unsigned)c);
        atomicAdd(&g_histA[c * NBA + (bits >> 20)], 1u);
    }

    int warp = tid >> 5;
    int lane = threadIdx.x & 31;
    int r0 = 2 * warp, r1 = 2 * warp + 1;
    if (r0 < B) {
        bool v1 = (r1 < B);
        const float4* f40 = (const float4*)(feat + (size_t)r0 * D);
        const float4* f41 = (const float4*)(feat + (size_t)(v1 ? r1 : r0) * D);
        const float4* w4 = (const float4*)w;
        float4 fv0[4], fv1[4];
#pragma unroll
        for (int j = 0; j < 4; j++) {
            fv0[j] = f40[lane + 32 * j];
            fv1[j] = f41[lane + 32 * j];
        }
        float s0[C], s1[C];
#pragma unroll
        for (int c = 0; c < C; c++) { s0[c] = 0.f; s1[c] = 0.f; }
#pragma unroll
        for (int j = 0; j < 4; j++) {
            float4 a = fv0[j], b = fv1[j];
#pragma unroll
            for (int c = 0; c < C; c++) {
                float4 wv = __ldg(&w4[c * (D / 4) + lane + 32 * j]);
                s0[c] += a.x * wv.x + a.y * wv.y + a.z * wv.z + a.w * wv.w;
                s1[c] += b.x * wv.x + b.y * wv.y + b.z * wv.z + b.w * wv.w;
            }
        }
#pragma unroll
        for (int o = 16; o; o >>= 1) {
#pragma unroll
            for (int c = 0; c < C; c++) {
                s0[c] += __shfl_xor_sync(0xffffffffu, s0[c], o);
                s1[c] += __shfl_xor_sync(0xffffffffu, s1[c], o);
            }
        }
        float pc0 = -INFINITY, pc1 = -INFINITY;
#pragma unroll
        for (int c = 0; c < C; c++)
            if (lane == c) { pc0 = s0[c] + bias[c]; pc1 = s1[c] + bias[c]; }

        float m0 = pc0, m1 = pc1;
#pragma unroll
        for (int o = 16; o; o >>= 1) {
            m0 = fmaxf(m0, __shfl_xor_sync(0xffffffffu, m0, o));
            m1 = fmaxf(m1, __shfl_xor_sync(0xffffffffu, m1, o));
        }
        float ex0 = (lane < C) ? expf(pc0 - m0) : 0.f;
        float tt0 = (lane < C) ? ex0 * (pc0 - m0) : 0.f;
        float ex1 = (lane < C) ? expf(pc1 - m1) : 0.f;
        float tt1 = (lane < C) ? ex1 * (pc1 - m1) : 0.f;
        float S0 = ex0, T0 = tt0, S1 = ex1, T1 = tt1;
#pragma unroll
        for (int o = 16; o; o >>= 1) {
            S0 += __shfl_xor_sync(0xffffffffu, S0, o);
            T0 += __shfl_xor_sync(0xffffffffu, T0, o);
            S1 += __shfl_xor_sync(0xffffffffu, S1, o);
            T1 += __shfl_xor_sync(0xffffffffu, T1, o);
        }
        float ent0 = logf(S0) - T0 / S0;
        float ent1 = logf(S1) - T1 / S1;
        unsigned bal0 = __ballot_sync(0xffffffffu, (lane < C) && (pc0 == m0));
        unsigned bal1 = __ballot_sync(0xffffffffu, (lane < C) && (pc1 == m1));
        int amax0 = __ffs(bal0) - 1;
        int amax1 = __ffs(bal1) - 1;
        if (lane == 0) {
            unsigned b0 = __float_as_uint(ent0);
            g_keys[N + r0] = make_uint2(b0, (unsigned)amax0);
            atomicAdd(&g_histA[amax0 * NBA + (b0 >> 20)], 1u);
            if (v1) {
                unsigned b1 = __float_as_uint(ent1);
                g_keys[N + r1] = make_uint2(b1, (unsigned)amax1);
                atomicAdd(&g_histA[amax1 * NBA + (b1 >> 20)], 1u);
            }
        }
    }

    // ---------------- tail: last C finishing blocks run scanA -------------
    __shared__ unsigned sh_ord;
    __syncthreads();
    __threadfence();
    __syncthreads();
    if (threadIdx.x == 0) sh_ord = atomicAdd(&g_done1, 1u);
    __syncthreads();
    unsigned nb = (unsigned)gridDim.x;
    unsigned ord = sh_ord;
    if (ord < nb - C) return;
    int c = (int)(ord - (nb - C));
    if (threadIdx.x == 0) {
        while (*(volatile unsigned*)&g_done1 < nb) {}
    }
    __syncthreads();
    __threadfence();

    // scanA body for class c
    int t = threadIdx.x;  // 256
    const unsigned* h = &g_histA[c * NBA];
    __shared__ unsigned chunk[256];
    __shared__ unsigned incl[256];
    unsigned s = 0;
#pragma unroll
    for (int j = 0; j < 16; j++) s += h[t * 16 + j];
    chunk[t] = s;
    incl[t] = s;
    g_Wc[c * D + t] = 0.f;
    g_Wc[c * D + t + 256] = 0.f;
    __syncthreads();
#pragma unroll
    for (int off = 1; off < 256; off <<= 1) {
        unsigned v = (t >= off) ? incl[t - off] : 0u;
        __syncthreads();
        incl[t] += v;
        __syncthreads();
    }
    int tot = (int)incl[255];
    int Kf = kptr[0];
    int k = tot < Kf ? tot : Kf;
    if (t == 0) {
        g_cnt[c] = 0;
        g_candcnt[c] = 0;
        if (k <= 0) { g_prefA[c] = 0u; g_kleft[c] = 0; }
    }
    if (k <= 0) return;
    int excl = (int)incl[t] - (int)chunk[t];
    if ((int)incl[t] >= k && excl < k) {
        int run = excl;
        for (int q = 0; q < 16; q++) {
            unsigned v = h[t * 16 + q];
            if (run + (int)v >= k) {
                g_prefA[c] = (unsigned)(t * 16 + q);
                g_kleft[c] = k - run;
                break;
            }
            run += (int)v;
        }
    }
}

// ---- kernel 2: compact + LAST-17-BLOCKS TAIL = selB -----------------------
__global__ void k_compact(int R) {
    __shared__ unsigned s_pref[C];
    if (threadIdx.x < C) s_pref[threadIdx.x] = g_prefA[threadIdx.x];
    __syncthreads();
    int tid = blockIdx.x * blockDim.x + threadIdx.x;
    int nth = gridDim.x * blockDim.x;
    for (int i = tid; i < R; i += nth) {
        uint2 kv = __ldg(&g_keys[i]);
        int c = (int)kv.y;
        unsigned bits = kv.x;
        unsigned b = bits >> 20;
        unsigned pa = s_pref[c];
        bool below = (b < pa);
        bool equal = (b == pa);
        unsigned act = __ballot_sync(0xffffffffu, below);
        if (below) {
            unsigned peers = __match_any_sync(act, c);
            int leader = __ffs(peers) - 1;
            int rank = __popc(peers & ((1u << (threadIdx.x & 31)) - 1u));
            int base = 0;
            if ((threadIdx.x & 31) == leader)
                base = atomicAdd(&g_cnt[c], __popc(peers));
            base = __shfl_sync(peers, base, leader);
            g_list[(size_t)c * LCAP + base + rank] = i;
        }
        unsigned act2 = __ballot_sync(0xffffffffu, equal);
        if (equal) {
            unsigned peers = __match_any_sync(act2, c);
            int leader = __ffs(peers) - 1;
            int rank = __popc(peers & ((1u << (threadIdx.x & 31)) - 1u));
            int base = 0;
            if ((threadIdx.x & 31) == leader)
                base = atomicAdd(&g_candcnt[c], __popc(peers));
            base = __shfl_sync(peers, base, leader);
            int p = base + rank;
            if (p < CANDCAP) g_cand[c][p] = i;
            atomicAdd(&g_lowhist[c * NLOW + ((bits >> 12) & 0xFFu)], 1u);
        }
    }

    // ---------------- tail: last C finishing blocks run selB --------------
    __shared__ unsigned sh_ord;
    __syncthreads();
    __threadfence();
    __syncthreads();
    if (threadIdx.x == 0) sh_ord = atomicAdd(&g_done2, 1u);
    __syncthreads();
    unsigned nb = (unsigned)gridDim.x;
    unsigned ord = sh_ord;
    if (ord < nb - C) return;
    int c = (int)(ord - (nb - C));
    if (threadIdx.x == 0) {
        while (*(volatile unsigned*)&g_done2 < nb) {}
    }
    __syncthreads();
    __threadfence();

    // selB body for class c
    int t = threadIdx.x;  // 256
    int k = g_kleft[c];
    int m = g_candcnt[c]; if (m > CANDCAP) m = CANDCAP;
    const int* lst = g_cand[c];

    __shared__ unsigned chunk[256];
    __shared__ unsigned incl[256];
    __shared__ int sh_thrbin, sh_kl2;
    __shared__ unsigned tkey[TIECAP];
    __shared__ int      tidx[TIECAP];
    __shared__ int      tcnt;

    if (k <= 0 || m <= 0) return;

    unsigned s = g_lowhist[c * NLOW + t];   // one bin per thread
    chunk[t] = s;
    incl[t] = s;
    if (t == 0) tcnt = 0;
    __syncthreads();
#pragma unroll
    for (int off = 1; off < 256; off <<= 1) {
        unsigned v = (t >= off) ? incl[t - off] : 0u;
        __syncthreads();
        incl[t] += v;
        __syncthreads();
    }
    int excl = (int)incl[t] - (int)chunk[t];
    if ((int)incl[t] >= k && excl < k) {
        sh_thrbin = t;
        sh_kl2 = k - excl;
    }
    __syncthreads();
    int thrbin = sh_thrbin;
    int kl2 = sh_kl2;

    for (int j = t; j < m; j += 256) {
        int idx = lst[j];
        unsigned bits = g_keys[idx].x;
        int lb = (int)((bits >> 12) & 0xFFu);
        if (lb < thrbin) {
            int p = atomicAdd(&g_cnt[c], 1);
            g_list[(size_t)c * LCAP + p] = idx;
        } else if (lb == thrbin) {
            int p = atomicAdd(&tcnt, 1);
            if (p < TIECAP) { tkey[p] = bits; tidx[p] = idx; }
        }
    }
    __syncthreads();
    int tc = tcnt;
    if (tc <= TIECAP) {
        for (int j = t; j < tc; j += 256) {
            unsigned key = tkey[j];
            int idx = tidx[j];
            int rank = 0;
            for (int q = 0; q < tc; q++) {
                unsigned kq = tkey[q];
                rank += (kq < key) || (kq == key && tidx[q] < idx);
            }
            if (rank < kl2) {
                int p = atomicAdd(&g_cnt[c], 1);
                g_list[(size_t)c * LCAP + p] = idx;
            }
        }
    } else {
        for (int j = t; j < m; j += 256) {
            int idx = lst[j];
            unsigned key = g_keys[idx].x;
            if ((int)((key >> 12) & 0xFFu) != thrbin) continue;
            int rank = 0;
            for (int q = 0; q < m; q++) {
                int iq = lst[q];
                unsigned kq = g_keys[iq].x;
                if ((int)((kq >> 12) & 0xFFu) != thrbin) continue;
                rank += (kq < key) || (kq == key && iq < idx);
            }
            if (rank < kl2) {
                int p = atomicAdd(&g_cnt[c], 1);
                g_list[(size_t)c * LCAP + p] = idx;
            }
        }
    }
}

// ---- kernel 3: support sums -> REDG into g_Wc; last block -> norms -------
__global__ void k_sum(const float* __restrict__ supports,
                      const float* __restrict__ feat, int N) {
    int c = blockIdx.y;
    int blk = blockIdx.x;
    int cnt = g_cnt[c]; if (cnt > LCAP) cnt = LCAP;
    int w = threadIdx.x >> 5, lane = threadIdx.x & 31;
    int wg = blk * 8 + w;
    const int* lst = &g_list[(size_t)c * LCAP];

    float acc[16];
#pragma unroll
    for (int j = 0; j < 16; j++) acc[j] = 0.f;

    for (int idx = wg; idx < cnt; idx += CH2 * 8) {
        int r = lst[idx];
        const float4* p = (const float4*)((r < N) ? supports + (size_t)r * D
                                                  : feat + (size_t)(r - N) * D);
        float4 v[4];
        float ss = 0.f;
#pragma unroll
        for (int j = 0; j < 4; j++) {
            v[j] = p[lane + 32 * j];
            ss += v[j].x * v[j].x + v[j].y * v[j].y + v[j].z * v[j].z + v[j].w * v[j].w;
        }
#pragma unroll
        for (int o = 16; o; o >>= 1) ss += __shfl_xor_sync(0xffffffffu, ss, o);
        float rn = 1.f / fmaxf(sqrtf(ss), 1e-12f);
#pragma unroll
        for (int j = 0; j < 4; j++) {
            acc[4 * j + 0] += v[j].x * rn;
            acc[4 * j + 1] += v[j].y * rn;
            acc[4 * j + 2] += v[j].z * rn;
            acc[4 * j + 3] += v[j].w * rn;
        }
    }

    __shared__ float sacc[D];
    for (int d = threadIdx.x; d < D; d += blockDim.x) sacc[d] = 0.f;
    __syncthreads();
#pragma unroll
    for (int j = 0; j < 4; j++) {
        int d = 4 * (lane + 32 * j);
        atomicAdd(&sacc[d + 0], acc[4 * j + 0]);
        atomicAdd(&sacc[d + 1], acc[4 * j + 1]);
        atomicAdd(&sacc[d + 2], acc[4 * j + 2]);
        atomicAdd(&sacc[d + 3], acc[4 * j + 3]);
    }
    __syncthreads();
    for (int d = threadIdx.x; d < D; d += blockDim.x)
        atomicAdd(&g_Wc[c * D + d], sacc[d]);   // REDG, no return

    __syncthreads();
    __threadfence();
    __syncthreads();
    __shared__ int amlast;
    if (threadIdx.x == 0) {
        unsigned v = atomicAdd(&g_done3, 1u);
        amlast = (v == (unsigned)(gridDim.x * gridDim.y - 1));
    }
    __syncthreads();
    if (!amlast) return;
    if (threadIdx.x == 0) g_done3 = 0u;
    for (int cc = w; cc < C; cc += 8) {
        float ss = 0.f;
#pragma unroll
        for (int j = 0; j < 16; j++) {
            float v = g_Wc[cc * D + lane + 32 * j];
            ss += v * v;
        }
#pragma unroll
        for (int o = 16; o; o >>= 1) ss += __shfl_xor_sync(0xffffffffu, ss, o);
        if (lane == 0)
            g_rn[cc] = 1.f / fmaxf(sqrtf(ss), 1e-12f);
    }
}

// ---- kernel 4: final GEMM (2 rows/warp); re-zero histograms + counters ----
__global__ void k_gemm2(const float* __restrict__ feat, float* __restrict__ out,
                        int B) {
    int tid = blockIdx.x * blockDim.x + threadIdx.x;
    int nth = gridDim.x * blockDim.x;
    for (int i = tid; i < C * NBA; i += nth) g_histA[i] = 0u;
    for (int i = tid; i < C * NLOW; i += nth) g_lowhist[i] = 0u;
    if (tid == 0) { g_done1 = 0u; g_done2 = 0u; }

    int warp = tid >> 5;
    int lane = threadIdx.x & 31;
    int r0 = 2 * warp, r1 = 2 * warp + 1;
    if (r0 >= B) return;
    bool v1 = (r1 < B);
    float rnl = (lane < C) ? g_rn[lane] : 0.f;
    const float4* f40 = (const float4*)(feat + (size_t)r0 * D);
    const float4* f41 = (const float4*)(feat + (size_t)(v1 ? r1 : r0) * D);
    const float4* w4 = (const float4*)g_Wc;
    float4 fv0[4], fv1[4];
#pragma unroll
    for (int j = 0; j < 4; j++) {
        fv0[j] = f40[lane + 32 * j];
        fv1[j] = f41[lane + 32 * j];
    }
    float s0[C], s1[C];
#pragma unroll
    for (int c = 0; c < C; c++) { s0[c] = 0.f; s1[c] = 0.f; }
#pragma unroll
    for (int j = 0; j < 4; j++) {
        float4 a = fv0[j], b = fv1[j];
#pragma unroll
        for (int c = 0; c < C; c++) {
            float4 wv = w4[c * (D / 4) + lane + 32 * j];
            s0[c] += a.x * wv.x + a.y * wv.y + a.z * wv.z + a.w * wv.w;
            s1[c] += b.x * wv.x + b.y * wv.y + b.z * wv.z + b.w * wv.w;
        }
    }
#pragma unroll
    for (int o = 16; o; o >>= 1) {
#pragma unroll
        for (int c = 0; c < C; c++) {
            s0[c] += __shfl_xor_sync(0xffffffffu, s0[c], o);
            s1[c] += __shfl_xor_sync(0xffffffffu, s1[c], o);
        }
    }
    float my0 = 0.f, my1 = 0.f;
#pragma unroll
    for (int c = 0; c < C; c++)
        if (lane == c) { my0 = s0[c]; my1 = s1[c]; }
    if (lane < C) {
        out[(size_t)r0 * C + lane] = my0 * rnl;
        if (v1) out[(size_t)r1 * C + lane] = my1 * rnl;
    }
}

// ---- launch ---------------------------------------------------------------
extern "C" void kernel_launch(void* const* d_in, const int* in_sizes, int n_in,
                              void* d_out, int out_size) {
    const float* feature  = (const float*)d_in[0];
    const float* clf_w    = (const float*)d_in[1];
    const float* clf_b    = (const float*)d_in[2];
    const float* supports = (const float*)d_in[3];
    const float* ent_bank = (const float*)d_in[4];
    const int*   labels   = (const int*)d_in[5];
    const int*   kptr     = (const int*)d_in[6];

    int Cc = in_sizes[2];          // 17
    int Dv = in_sizes[1] / Cc;     // 512
    int B  = in_sizes[0] / Dv;     // 4096
    int N  = in_sizes[4];          // 100000
    int R  = N + B;
    (void)n_in; (void)out_size; (void)Dv;

    float* out = (float*)d_out;

    int blkG = (B * 16 + 255) / 256;   // 256 blocks (2 rows per warp)
    k_logits<<<blkG, 256>>>(feature, clf_w, clf_b, ent_bank, labels, B, N, kptr);
    k_compact<<<(R + 255) / 256, 256>>>(R);
    dim3 g3(CH2, C);
    k_sum<<<g3, 256>>>(supports, feature, N);
    k_gemm2<<<blkG, 256>>>(feature, out, B);
}

// round 16
// speedup vs baseline: 1.0867x; 1.0867x over previous
#include <cuda_runtime.h>
#include <math.h>
#include <stdint.h>

#define D 512
#define C 17
#define RMAX 131072
#define NBA 4096
#define NLOW 256
#define CANDCAP 32768
#define TIECAP 512
#define LCAP 4096
#define CH2 64

// ---------------- device scratch (static; zero-init at module load) -------
__device__ uint2    g_keys[RMAX];        // {entropy bits, class}
__device__ unsigned g_histA[C * NBA];    // re-zeroed by k_gemm2 each run
__device__ unsigned g_lowhist[C * NLOW]; // re-zeroed by k_gemm2 each run
__device__ unsigned g_prefA[C];
__device__ int      g_kleft[C];
__device__ int      g_cnt[C];
__device__ int      g_candcnt[C];
__device__ int      g_cand[C][CANDCAP];
__device__ int      g_list[(size_t)C * LCAP];
__device__ float    g_Wc[C * D];         // zeroed in k_scanA, REDG in k_sum
__device__ float    g_rn[C];
__device__ unsigned g_done;              // reset by k_sum last block

// ---- kernel 1: bank keys + new-row logits/entropy/argmax, hist pass A ----
__global__ void k_logits(const float* __restrict__ feat,
                         const float* __restrict__ w,
                         const float* __restrict__ bias,
                         const float* __restrict__ entbank,
                         const int*   __restrict__ labels,
                         int B, int N) {
    int tid = blockIdx.x * blockDim.x + threadIdx.x;
    int nth = gridDim.x * blockDim.x;
    for (int i = tid; i < N; i += nth) {
        unsigned bits = __float_as_uint(entbank[i]);  // entropies >= 0: monotone
        int c = labels[i];
        g_keys[i] = make_uint2(bits, (unsigned)c);
        atomicAdd(&g_histA[c * NBA + (bits >> 20)], 1u);
    }

    int warp = tid >> 5;
    int lane = threadIdx.x & 31;
    if (warp >= B) return;

    const float4* f4 = (const float4*)(feat + (size_t)warp * D);
    const float4* w4 = (const float4*)w;
    float4 fv[4];
#pragma unroll
    for (int j = 0; j < 4; j++) fv[j] = f4[lane + 32 * j];

    float s[C];
#pragma unroll
    for (int c = 0; c < C; c++) s[c] = 0.f;
#pragma unroll
    for (int j = 0; j < 4; j++) {
        float4 fj = fv[j];
#pragma unroll
        for (int c = 0; c < C; c++) {
            float4 wv = __ldg(&w4[c * (D / 4) + lane + 32 * j]);
            s[c] += fj.x * wv.x + fj.y * wv.y + fj.z * wv.z + fj.w * wv.w;
        }
    }
#pragma unroll
    for (int o = 16; o; o >>= 1) {
#pragma unroll
        for (int c = 0; c < C; c++)
            s[c] += __shfl_xor_sync(0xffffffffu, s[c], o);
    }
    float pc = -INFINITY;
#pragma unroll
    for (int c = 0; c < C; c++)
        if (lane == c) pc = s[c] + bias[c];

    float m = pc;
#pragma unroll
    for (int o = 16; o; o >>= 1) m = fmaxf(m, __shfl_xor_sync(0xffffffffu, m, o));

    float ex = (lane < C) ? expf(pc - m) : 0.f;
    float tt = (lane < C) ? ex * (pc - m) : 0.f;
    float S = ex, T = tt;
#pragma unroll
    for (int o = 16; o; o >>= 1) {
        S += __shfl_xor_sync(0xffffffffu, S, o);
        T += __shfl_xor_sync(0xffffffffu, T, o);
    }
    float ent = logf(S) - T / S;
    unsigned bal = __ballot_sync(0xffffffffu, (lane < C) && (pc == m));
    int amax = __ffs(bal) - 1;
    if (lane == 0) {
        unsigned bits = __float_as_uint(ent);
        g_keys[N + warp] = make_uint2(bits, (unsigned)amax);
        atomicAdd(&g_histA[amax * NBA + (bits >> 20)], 1u);
    }
}

// ---- kernel 2: scan pass A -> 12-bit bin per class; zero g_Wc ------------
__global__ void k_scanA(const int* __restrict__ kptr) {
    cudaGridDependencySynchronize();
    int c = blockIdx.x;
    int t = threadIdx.x;  // 256
    const unsigned* h = &g_histA[c * NBA];
    __shared__ unsigned chunk[256];
    __shared__ unsigned incl[256];
    unsigned s = 0;
#pragma unroll
    for (int j = 0; j < 16; j++) s += h[t * 16 + j];
    chunk[t] = s;
    incl[t] = s;
    g_Wc[c * D + t] = 0.f;
    g_Wc[c * D + t + 256] = 0.f;
    __syncthreads();
#pragma unroll
    for (int off = 1; off < 256; off <<= 1) {
        unsigned v = (t >= off) ? incl[t - off] : 0u;
        __syncthreads();
        incl[t] += v;
        __syncthreads();
    }
    int tot = (int)incl[255];
    int Kf = kptr[0];
    int k = tot < Kf ? tot : Kf;
    if (t == 0) {
        g_cnt[c] = 0;
        g_candcnt[c] = 0;
        if (k <= 0) { g_prefA[c] = 0u; g_kleft[c] = 0; }
    }
    if (k <= 0) return;
    int excl = (int)incl[t] - (int)chunk[t];
    if ((int)incl[t] >= k && excl < k) {
        int run = excl;
        for (int q = 0; q < 16; q++) {
            unsigned v = h[t * 16 + q];
            if (run + (int)v >= k) {
                g_prefA[c] = (unsigned)(t * 16 + q);
                g_kleft[c] = k - run;
                break;
            }
            run += (int)v;
        }
    }
}

// ---- kernel 3: compact below rows + candidates + 8-bit sub-histogram -----
__global__ void k_compact(int R) {
    cudaGridDependencySynchronize();
    __shared__ unsigned s_pref[C];
    if (threadIdx.x < C) s_pref[threadIdx.x] = g_prefA[threadIdx.x];
    __syncthreads();
    int tid = blockIdx.x * blockDim.x + threadIdx.x;
    int nth = gridDim.x * blockDim.x;
    for (int i = tid; i < R; i += nth) {
        uint2 kv = __ldg(&g_keys[i]);
        int c = (int)kv.y;
        unsigned bits = kv.x;
        unsigned b = bits >> 20;
        unsigned pa = s_pref[c];
        bool below = (b < pa);
        bool equal = (b == pa);
        unsigned act = __ballot_sync(0xffffffffu, below);
        if (below) {
            unsigned peers = __match_any_sync(act, c);
            int leader = __ffs(peers) - 1;
            int rank = __popc(peers & ((1u << (threadIdx.x & 31)) - 1u));
            int base = 0;
            if ((threadIdx.x & 31) == leader)
                base = atomicAdd(&g_cnt[c], __popc(peers));
            base = __shfl_sync(peers, base, leader);
            g_list[(size_t)c * LCAP + base + rank] = i;
        }
        unsigned act2 = __ballot_sync(0xffffffffu, equal);
        if (equal) {
            unsigned peers = __match_any_sync(act2, c);
            int leader = __ffs(peers) - 1;
            int rank = __popc(peers & ((1u << (threadIdx.x & 31)) - 1u));
            int base = 0;
            if ((threadIdx.x & 31) == leader)
                base = atomicAdd(&g_candcnt[c], __popc(peers));
            base = __shfl_sync(peers, base, leader);
            int p = base + rank;
            if (p < CANDCAP) g_cand[c][p] = i;
            atomicAdd(&g_lowhist[c * NLOW + ((bits >> 12) & 0xFFu)], 1u);
        }
    }
}

// ---- kernel 4: exact select via 256-bin scan + tiny tie ranking ----------
__global__ void k_selB() {
    cudaGridDependencySynchronize();
    int c = blockIdx.x;
    int t = threadIdx.x;  // 256
    int k = g_kleft[c];
    int m = g_candcnt[c]; if (m > CANDCAP) m = CANDCAP;
    const int* lst = g_cand[c];

    __shared__ unsigned chunk[256];
    __shared__ unsigned incl[256];
    __shared__ int sh_thrbin, sh_kl2;
    __shared__ unsigned tkey[TIECAP];
    __shared__ int      tidx[TIECAP];
    __shared__ int      tcnt;

    if (k <= 0 || m <= 0) return;

    unsigned s = g_lowhist[c * NLOW + t];   // one bin per thread
    chunk[t] = s;
    incl[t] = s;
    if (t == 0) tcnt = 0;
    __syncthreads();
#pragma unroll
    for (int off = 1; off < 256; off <<= 1) {
        unsigned v = (t >= off) ? incl[t - off] : 0u;
        __syncthreads();
        incl[t] += v;
        __syncthreads();
    }
    int excl = (int)incl[t] - (int)chunk[t];
    if ((int)incl[t] >= k && excl < k) {
        sh_thrbin = t;
        sh_kl2 = k - excl;
    }
    __syncthreads();
    int thrbin = sh_thrbin;
    int kl2 = sh_kl2;

    for (int j = t; j < m; j += 256) {
        int idx = lst[j];
        unsigned bits = g_keys[idx].x;
        int lb = (int)((bits >> 12) & 0xFFu);
        if (lb < thrbin) {
            int p = atomicAdd(&g_cnt[c], 1);
            g_list[(size_t)c * LCAP + p] = idx;
        } else if (lb == thrbin) {
            int p = atomicAdd(&tcnt, 1);
            if (p < TIECAP) { tkey[p] = bits; tidx[p] = idx; }
        }
    }
    __syncthreads();
    int tc = tcnt;
    if (tc <= TIECAP) {
        for (int j = t; j < tc; j += 256) {
            unsigned key = tkey[j];
            int idx = tidx[j];
            int rank = 0;
            for (int q = 0; q < tc; q++) {
                unsigned kq = tkey[q];
                rank += (kq < key) || (kq == key && tidx[q] < idx);
            }
            if (rank < kl2) {
                int p = atomicAdd(&g_cnt[c], 1);
                g_list[(size_t)c * LCAP + p] = idx;
            }
        }
    } else {
        // pathological: tie bin overflow -> rank against full candidate list
        for (int j = t; j < m; j += 256) {
            int idx = lst[j];
            unsigned key = g_keys[idx].x;
            if ((int)((key >> 12) & 0xFFu) != thrbin) continue;
            int rank = 0;
            for (int q = 0; q < m; q++) {
                int iq = lst[q];
                unsigned kq = g_keys[iq].x;
                if ((int)((kq >> 12) & 0xFFu) != thrbin) continue;
                rank += (kq < key) || (kq == key && iq < idx);
            }
            if (rank < kl2) {
                int p = atomicAdd(&g_cnt[c], 1);
                g_list[(size_t)c * LCAP + p] = idx;
            }
        }
    }
}

// ---- kernel 5: support sums -> REDG into g_Wc; last block -> norms -------
__global__ void k_sum(const float* __restrict__ supports,
                      const float* __restrict__ feat, int N) {
    cudaGridDependencySynchronize();
    int c = blockIdx.y;
    int blk = blockIdx.x;
    int cnt = g_cnt[c]; if (cnt > LCAP) cnt = LCAP;
    int w = threadIdx.x >> 5, lane = threadIdx.x & 31;
    int wg = blk * 8 + w;
    const int* lst = &g_list[(size_t)c * LCAP];

    float acc[16];
#pragma unroll
    for (int j = 0; j < 16; j++) acc[j] = 0.f;

    for (int idx = wg; idx < cnt; idx += CH2 * 8) {
        int r = lst[idx];
        const float4* p = (const float4*)((r < N) ? supports + (size_t)r * D
                                                  : feat + (size_t)(r - N) * D);
        float4 v[4];
        float ss = 0.f;
#pragma unroll
        for (int j = 0; j < 4; j++) {
            v[j] = p[lane + 32 * j];
            ss += v[j].x * v[j].x + v[j].y * v[j].y + v[j].z * v[j].z + v[j].w * v[j].w;
        }
#pragma unroll
        for (int o = 16; o; o >>= 1) ss += __shfl_xor_sync(0xffffffffu, ss, o);
        float rn = 1.f / fmaxf(sqrtf(ss), 1e-12f);
#pragma unroll
        for (int j = 0; j < 4; j++) {
            acc[4 * j + 0] += v[j].x * rn;
            acc[4 * j + 1] += v[j].y * rn;
            acc[4 * j + 2] += v[j].z * rn;
            acc[4 * j + 3] += v[j].w * rn;
        }
    }

    __shared__ float sacc[D];
    for (int d = threadIdx.x; d < D; d += blockDim.x) sacc[d] = 0.f;
    __syncthreads();
#pragma unroll
    for (int j = 0; j < 4; j++) {
        int d = 4 * (lane + 32 * j);
        atomicAdd(&sacc[d + 0], acc[4 * j + 0]);
        atomicAdd(&sacc[d + 1], acc[4 * j + 1]);
        atomicAdd(&sacc[d + 2], acc[4 * j + 2]);
        atomicAdd(&sacc[d + 3], acc[4 * j + 3]);
    }
    __syncthreads();
    for (int d = threadIdx.x; d < D; d += blockDim.x)
        atomicAdd(&g_Wc[c * D + d], sacc[d]);   // REDG, no return

    // all threads fence their REDGs, then one thread claims the done slot
    __syncthreads();
    __threadfence();
    __syncthreads();
    __shared__ int amlast;
    if (threadIdx.x == 0) {
        unsigned v = atomicAdd(&g_done, 1u);
        amlast = (v == (unsigned)(gridDim.x * gridDim.y - 1));
    }
    __syncthreads();
    if (!amlast) return;
    if (threadIdx.x == 0) g_done = 0u;
    for (int cc = w; cc < C; cc += 8) {
        float ss = 0.f;
#pragma unroll
        for (int j = 0; j < 16; j++) {
            float v = g_Wc[cc * D + lane + 32 * j];
            ss += v * v;
        }
#pragma unroll
        for (int o = 16; o; o >>= 1) ss += __shfl_xor_sync(0xffffffffu, ss, o);
        if (lane == 0)
            g_rn[cc] = 1.f / fmaxf(sqrtf(ss), 1e-12f);
    }
}

// ---- kernel 6: final GEMM; PDL prologue prefetches feature + zeros hists --
__global__ void k_gemm2(const float* __restrict__ feat, float* __restrict__ out,
                        int B) {
    int tid = blockIdx.x * blockDim.x + threadIdx.x;
    int nth = gridDim.x * blockDim.x;

    // ---- pre-sync prologue: overlaps k_sum execution ----
    // (histograms were last read by k_selB, which completed before k_sum began)
    for (int i = tid; i < C * NBA; i += nth) g_histA[i] = 0u;
    for (int i = tid; i < C * NLOW; i += nth) g_lowhist[i] = 0u;

    int warp = tid >> 5;
    int lane = threadIdx.x & 31;
    float4 fv[4];
    const float4* f4 = (const float4*)(feat + (size_t)(warp < B ? warp : 0) * D);
#pragma unroll
    for (int j = 0; j < 4; j++) fv[j] = f4[lane + 32 * j];

    // ---- wait for k_sum's g_Wc / g_rn ----
    cudaGridDependencySynchronize();

    if (warp >= B) return;
    float rnl = (lane < C) ? g_rn[lane] : 0.f;
    const float4* w4 = (const float4*)g_Wc;
    float s[C];
#pragma unroll
    for (int c = 0; c < C; c++) s[c] = 0.f;
#pragma unroll
    for (int j = 0; j < 4; j++) {
        float4 fj = fv[j];
#pragma unroll
        for (int c = 0; c < C; c++) {
            float4 wv = w4[c * (D / 4) + lane + 32 * j];
            s[c] += fj.x * wv.x + fj.y * wv.y + fj.z * wv.z + fj.w * wv.w;
        }
    }
#pragma unroll
    for (int o = 16; o; o >>= 1) {
#pragma unroll
        for (int c = 0; c < C; c++)
            s[c] += __shfl_xor_sync(0xffffffffu, s[c], o);
    }
    float myv = 0.f;
#pragma unroll
    for (int c = 0; c < C; c++)
        if (lane == c) myv = s[c];
    if (lane < C) out[(size_t)warp * C + lane] = myv * rnl;
}

// ---- host helper: launch with programmatic stream serialization ----------
template <typename... Args>
static void launch_pdl(void (*kern)(Args...), dim3 grid, dim3 block,
                       Args... args) {
    cudaLaunchConfig_t cfg = {};
    cfg.gridDim = grid;
    cfg.blockDim = block;
    cfg.dynamicSmemBytes = 0;
    cfg.stream = 0;
    cudaLaunchAttribute attr[1];
    attr[0].id = cudaLaunchAttributeProgrammaticStreamSerialization;
    attr[0].val.programmaticStreamSerializationAllowed = 1;
    cfg.attrs = attr;
    cfg.numAttrs = 1;
    cudaLaunchKernelEx(&cfg, kern, args...);
}

// ---- launch ---------------------------------------------------------------
extern "C" void kernel_launch(void* const* d_in, const int* in_sizes, int n_in,
                              void* d_out, int out_size) {
    const float* feature  = (const float*)d_in[0];
    const float* clf_w    = (const float*)d_in[1];
    const float* clf_b    = (const float*)d_in[2];
    const float* supports = (const float*)d_in[3];
    const float* ent_bank = (const float*)d_in[4];
    const int*   labels   = (const int*)d_in[5];
    const int*   kptr     = (const int*)d_in[6];

    int Cc = in_sizes[2];          // 17
    int Dv = in_sizes[1] / Cc;     // 512
    int B  = in_sizes[0] / Dv;     // 4096
    int N  = in_sizes[4];          // 100000
    int R  = N + B;
    (void)n_in; (void)out_size; (void)Dv;

    float* out = (float*)d_out;

    int blk1 = (B * 32 + 255) / 256;   // 512 blocks
    k_logits<<<blk1, 256>>>(feature, clf_w, clf_b, ent_bank, labels, B, N);
    launch_pdl(k_scanA, dim3(C), dim3(256), kptr);
    launch_pdl(k_compact, dim3((R + 255) / 256), dim3(256), R);
    launch_pdl(k_selB, dim3(C), dim3(256));
    launch_pdl(k_sum, dim3(CH2, C), dim3(256), supports, feature, N);
    launch_pdl(k_gemm2, dim3(blk1), dim3(256), feature, out, B);
}

// round 17
// speedup vs baseline: 1.1089x; 1.0205x over previous
#include <cuda_runtime.h>
#include <math.h>
#include <stdint.h>

#define D 512
#define C 17
#define RMAX 131072
#define NBA 4096
#define NLOW 256
#define CANDCAP 32768
#define TIECAP 512
#define LCAP 4096
#define CH2 64

typedef unsigned long long u64;

// ---------------- device scratch (static; zero-init at module load) -------
__device__ uint2    g_keys[RMAX];        // {entropy bits, class}
__device__ unsigned g_histA[C * NBA];    // re-zeroed by k_gemm2 each run
__device__ unsigned g_lowhist[C * NLOW]; // re-zeroed by k_gemm2 each run
__device__ unsigned g_prefA[C];
__device__ int      g_kleft[C];
__device__ int      g_cnt[C];
__device__ int      g_candcnt[C];
__device__ u64      g_cand[C][CANDCAP];  // packed (bits<<32)|idx
__device__ int      g_list[(size_t)C * LCAP];
__device__ float    g_Wc[C * D];         // zeroed in k_scanA, REDG in k_sum
__device__ float    g_rn[C];
__device__ unsigned g_done;              // reset by k_sum last block

// ---- kernel 1: bank keys + new-row logits/entropy/argmax, hist pass A ----
__global__ void k_logits(const float* __restrict__ feat,
                         const float* __restrict__ w,
                         const float* __restrict__ bias,
                         const float* __restrict__ entbank,
                         const int*   __restrict__ labels,
                         int B, int N) {
    int tid = blockIdx.x * blockDim.x + threadIdx.x;
    int nth = gridDim.x * blockDim.x;
    for (int i = tid; i < N; i += nth) {
        unsigned bits = __float_as_uint(entbank[i]);  // entropies >= 0: monotone
        int c = labels[i];
        g_keys[i] = make_uint2(bits, (unsigned)c);
        atomicAdd(&g_histA[c * NBA + (bits >> 20)], 1u);
    }

    int warp = tid >> 5;
    int lane = threadIdx.x & 31;
    if (warp >= B) return;

    const float4* f4 = (const float4*)(feat + (size_t)warp * D);
    const float4* w4 = (const float4*)w;
    float4 fv[4];
#pragma unroll
    for (int j = 0; j < 4; j++) fv[j] = f4[lane + 32 * j];

    float s[C];
#pragma unroll
    for (int c = 0; c < C; c++) s[c] = 0.f;
#pragma unroll
    for (int j = 0; j < 4; j++) {
        float4 fj = fv[j];
#pragma unroll
        for (int c = 0; c < C; c++) {
            float4 wv = __ldg(&w4[c * (D / 4) + lane + 32 * j]);
            s[c] += fj.x * wv.x + fj.y * wv.y + fj.z * wv.z + fj.w * wv.w;
        }
    }
#pragma unroll
    for (int o = 16; o; o >>= 1) {
#pragma unroll
        for (int c = 0; c < C; c++)
            s[c] += __shfl_xor_sync(0xffffffffu, s[c], o);
    }
    float pc = -INFINITY;
#pragma unroll
    for (int c = 0; c < C; c++)
        if (lane == c) pc = s[c] + bias[c];

    float m = pc;
#pragma unroll
    for (int o = 16; o; o >>= 1) m = fmaxf(m, __shfl_xor_sync(0xffffffffu, m, o));

    float ex = (lane < C) ? expf(pc - m) : 0.f;
    float tt = (lane < C) ? ex * (pc - m) : 0.f;
    float S = ex, T = tt;
#pragma unroll
    for (int o = 16; o; o >>= 1) {
        S += __shfl_xor_sync(0xffffffffu, S, o);
        T += __shfl_xor_sync(0xffffffffu, T, o);
    }
    float ent = logf(S) - T / S;
    unsigned bal = __ballot_sync(0xffffffffu, (lane < C) && (pc == m));
    int amax = __ffs(bal) - 1;
    if (lane == 0) {
        unsigned bits = __float_as_uint(ent);
        g_keys[N + warp] = make_uint2(bits, (unsigned)amax);
        atomicAdd(&g_histA[amax * NBA + (bits >> 20)], 1u);
    }
}

// ---- kernel 2: scan pass A -> 12-bit bin per class; zero g_Wc ------------
__global__ void k_scanA(const int* __restrict__ kptr) {
    cudaGridDependencySynchronize();
    int c = blockIdx.x;
    int t = threadIdx.x;  // 256
    const unsigned* h = &g_histA[c * NBA];
    __shared__ unsigned chunk[256];
    __shared__ unsigned incl[256];
    unsigned s = 0;
#pragma unroll
    for (int j = 0; j < 16; j++) s += h[t * 16 + j];
    chunk[t] = s;
    incl[t] = s;
    g_Wc[c * D + t] = 0.f;
    g_Wc[c * D + t + 256] = 0.f;
    __syncthreads();
#pragma unroll
    for (int off = 1; off < 256; off <<= 1) {
        unsigned v = (t >= off) ? incl[t - off] : 0u;
        __syncthreads();
        incl[t] += v;
        __syncthreads();
    }
    int tot = (int)incl[255];
    int Kf = kptr[0];
    int k = tot < Kf ? tot : Kf;
    if (t == 0) {
        g_cnt[c] = 0;
        g_candcnt[c] = 0;
        if (k <= 0) { g_prefA[c] = 0u; g_kleft[c] = 0; }
    }
    if (k <= 0) return;
    int excl = (int)incl[t] - (int)chunk[t];
    if ((int)incl[t] >= k && excl < k) {
        int run = excl;
        for (int q = 0; q < 16; q++) {
            unsigned v = h[t * 16 + q];
            if (run + (int)v >= k) {
                g_prefA[c] = (unsigned)(t * 16 + q);
                g_kleft[c] = k - run;
                break;
            }
            run += (int)v;
        }
    }
}

// ---- kernel 3: compact below rows + packed candidates + 8-bit subhist ----
__global__ void k_compact(int R) {
    cudaGridDependencySynchronize();
    __shared__ unsigned s_pref[C];
    if (threadIdx.x < C) s_pref[threadIdx.x] = g_prefA[threadIdx.x];
    __syncthreads();
    int tid = blockIdx.x * blockDim.x + threadIdx.x;
    int nth = gridDim.x * blockDim.x;
    for (int i = tid; i < R; i += nth) {
        uint2 kv = __ldg(&g_keys[i]);
        int c = (int)kv.y;
        unsigned bits = kv.x;
        unsigned b = bits >> 20;
        unsigned pa = s_pref[c];
        bool below = (b < pa);
        bool equal = (b == pa);
        unsigned act = __ballot_sync(0xffffffffu, below);
        if (below) {
            unsigned peers = __match_any_sync(act, c);
            int leader = __ffs(peers) - 1;
            int rank = __popc(peers & ((1u << (threadIdx.x & 31)) - 1u));
            int base = 0;
            if ((threadIdx.x & 31) == leader)
                base = atomicAdd(&g_cnt[c], __popc(peers));
            base = __shfl_sync(peers, base, leader);
            g_list[(size_t)c * LCAP + base + rank] = i;
        }
        unsigned act2 = __ballot_sync(0xffffffffu, equal);
        if (equal) {
            unsigned peers = __match_any_sync(act2, c);
            int leader = __ffs(peers) - 1;
            int rank = __popc(peers & ((1u << (threadIdx.x & 31)) - 1u));
            int base = 0;
            if ((threadIdx.x & 31) == leader)
                base = atomicAdd(&g_candcnt[c], __popc(peers));
            base = __shfl_sync(peers, base, leader);
            int p = base + rank;
            if (p < CANDCAP)
                g_cand[c][p] = ((u64)bits << 32) | (unsigned)i;
            atomicAdd(&g_lowhist[c * NLOW + ((bits >> 12) & 0xFFu)], 1u);
        }
    }
}

// ---- kernel 4: exact select via 256-bin scan + packed tie ranking --------
__global__ void k_selB() {
    cudaGridDependencySynchronize();
    int c = blockIdx.x;
    int t = threadIdx.x;  // 256
    int k = g_kleft[c];
    int m = g_candcnt[c]; if (m > CANDCAP) m = CANDCAP;
    const u64* lst = g_cand[c];

    __shared__ unsigned chunk[256];
    __shared__ unsigned incl[256];
    __shared__ int sh_thrbin, sh_kl2;
    __shared__ u64 tpack[TIECAP];
    __shared__ int tcnt;

    if (k <= 0 || m <= 0) return;

    unsigned s = g_lowhist[c * NLOW + t];   // one bin per thread
    chunk[t] = s;
    incl[t] = s;
    if (t == 0) tcnt = 0;
    __syncthreads();
#pragma unroll
    for (int off = 1; off < 256; off <<= 1) {
        unsigned v = (t >= off) ? incl[t - off] : 0u;
        __syncthreads();
        incl[t] += v;
        __syncthreads();
    }
    int excl = (int)incl[t] - (int)chunk[t];
    if ((int)incl[t] >= k && excl < k) {
        sh_thrbin = t;
        sh_kl2 = k - excl;
    }
    __syncthreads();
    int thrbin = sh_thrbin;
    int kl2 = sh_kl2;

    for (int j = t; j < m; j += 256) {
        u64 pk = lst[j];                       // single LDG.64
        unsigned bits = (unsigned)(pk >> 32);
        int lb = (int)((bits >> 12) & 0xFFu);
        if (lb < thrbin) {
            int p = atomicAdd(&g_cnt[c], 1);
            g_list[(size_t)c * LCAP + p] = (int)(unsigned)pk;
        } else if (lb == thrbin) {
            int p = atomicAdd(&tcnt, 1);
            if (p < TIECAP) tpack[p] = pk;
        }
    }
    __syncthreads();
    int tc = tcnt;
    if (tc <= TIECAP) {
        // packed u64 ascending == (bits asc, idx asc)
        for (int j = t; j < tc; j += 256) {
            u64 pk = tpack[j];
            int rank = 0;
            for (int q = 0; q < tc; q++) rank += (tpack[q] < pk);
            if (rank < kl2) {
                int p = atomicAdd(&g_cnt[c], 1);
                g_list[(size_t)c * LCAP + p] = (int)(unsigned)pk;
            }
        }
    } else {
        // pathological: tie bin overflow -> rank against full candidate list
        for (int j = t; j < m; j += 256) {
            u64 pk = lst[j];
            unsigned bits = (unsigned)(pk >> 32);
            if ((int)((bits >> 12) & 0xFFu) != thrbin) continue;
            int rank = 0;
            for (int q = 0; q < m; q++) {
                u64 pq = lst[q];
                unsigned bq = (unsigned)(pq >> 32);
                if ((int)((bq >> 12) & 0xFFu) != thrbin) continue;
                rank += (pq < pk);
            }
            if (rank < kl2) {
                int p = atomicAdd(&g_cnt[c], 1);
                g_list[(size_t)c * LCAP + p] = (int)(unsigned)pk;
            }
        }
    }
}

// ---- kernel 5: support sums -> REDG into g_Wc; last block -> norms -------
__global__ void k_sum(const float* __restrict__ supports,
                      const float* __restrict__ feat, int N) {
    cudaGridDependencySynchronize();
    int c = blockIdx.y;
    int blk = blockIdx.x;
    int cnt = g_cnt[c]; if (cnt > LCAP) cnt = LCAP;
    int w = threadIdx.x >> 5, lane = threadIdx.x & 31;
    int wg = blk * 8 + w;
    const int* lst = &g_list[(size_t)c * LCAP];

    float acc[16];
#pragma unroll
    for (int j = 0; j < 16; j++) acc[j] = 0.f;

    for (int idx = wg; idx < cnt; idx += CH2 * 8) {
        int r = lst[idx];
        const float4* p = (const float4*)((r < N) ? supports + (size_t)r * D
                                                  : feat + (size_t)(r - N) * D);
        float4 v[4];
        float ss = 0.f;
#pragma unroll
        for (int j = 0; j < 4; j++) {
            v[j] = p[lane + 32 * j];
            ss += v[j].x * v[j].x + v[j].y * v[j].y + v[j].z * v[j].z + v[j].w * v[j].w;
        }
#pragma unroll
        for (int o = 16; o; o >>= 1) ss += __shfl_xor_sync(0xffffffffu, ss, o);
        float rn = 1.f / fmaxf(sqrtf(ss), 1e-12f);
#pragma unroll
        for (int j = 0; j < 4; j++) {
            acc[4 * j + 0] += v[j].x * rn;
            acc[4 * j + 1] += v[j].y * rn;
            acc[4 * j + 2] += v[j].z * rn;
            acc[4 * j + 3] += v[j].w * rn;
        }
    }

    __shared__ float sacc[D];
    for (int d = threadIdx.x; d < D; d += blockDim.x) sacc[d] = 0.f;
    __syncthreads();
#pragma unroll
    for (int j = 0; j < 4; j++) {
        int d = 4 * (lane + 32 * j);
        atomicAdd(&sacc[d + 0], acc[4 * j + 0]);
        atomicAdd(&sacc[d + 1], acc[4 * j + 1]);
        atomicAdd(&sacc[d + 2], acc[4 * j + 2]);
        atomicAdd(&sacc[d + 3], acc[4 * j + 3]);
    }
    __syncthreads();
    for (int d = threadIdx.x; d < D; d += blockDim.x)
        atomicAdd(&g_Wc[c * D + d], sacc[d]);   // REDG, no return

    // all threads fence their REDGs, then one thread claims the done slot
    __syncthreads();
    __threadfence();
    __syncthreads();
    __shared__ int amlast;
    if (threadIdx.x == 0) {
        unsigned v = atomicAdd(&g_done, 1u);
        amlast = (v == (unsigned)(gridDim.x * gridDim.y - 1));
    }
    __syncthreads();
    if (!amlast) return;
    if (threadIdx.x == 0) g_done = 0u;
    for (int cc = w; cc < C; cc += 8) {
        float ss = 0.f;
#pragma unroll
        for (int j = 0; j < 16; j++) {
            float v = g_Wc[cc * D + lane + 32 * j];
            ss += v * v;
        }
#pragma unroll
        for (int o = 16; o; o >>= 1) ss += __shfl_xor_sync(0xffffffffu, ss, o);
        if (lane == 0)
            g_rn[cc] = 1.f / fmaxf(sqrtf(ss), 1e-12f);
    }
}

// ---- kernel 6: final GEMM; PDL prologue prefetches feature + zeros hists --
__global__ void k_gemm2(const float* __restrict__ feat, float* __restrict__ out,
                        int B) {
    int tid = blockIdx.x * blockDim.x + threadIdx.x;
    int nth = gridDim.x * blockDim.x;

    // ---- pre-sync prologue: overlaps k_sum execution ----
    // (histograms were last read by k_selB, which completed before k_sum began)
    for (int i = tid; i < C * NBA; i += nth) g_histA[i] = 0u;
    for (int i = tid; i < C * NLOW; i += nth) g_lowhist[i] = 0u;

    int warp = tid >> 5;
    int lane = threadIdx.x & 31;
    float4 fv[4];
    const float4* f4 = (const float4*)(feat + (size_t)(warp < B ? warp : 0) * D);
#pragma unroll
    for (int j = 0; j < 4; j++) fv[j] = f4[lane + 32 * j];

    // ---- wait for k_sum's g_Wc / g_rn ----
    cudaGridDependencySynchronize();

    if (warp >= B) return;
    float rnl = (lane < C) ? g_rn[lane] : 0.f;
    const float4* w4 = (const float4*)g_Wc;
    float s[C];
#pragma unroll
    for (int c = 0; c < C; c++) s[c] = 0.f;
#pragma unroll
    for (int j = 0; j < 4; j++) {
        float4 fj = fv[j];
#pragma unroll
        for (int c = 0; c < C; c++) {
            float4 wv = w4[c * (D / 4) + lane + 32 * j];
            s[c] += fj.x * wv.x + fj.y * wv.y + fj.z * wv.z + fj.w * wv.w;
        }
    }
#pragma unroll
    for (int o = 16; o; o >>= 1) {
#pragma unroll
        for (int c = 0; c < C; c++)
            s[c] += __shfl_xor_sync(0xffffffffu, s[c], o);
    }
    float myv = 0.f;
#pragma unroll
    for (int c = 0; c < C; c++)
        if (lane == c) myv = s[c];
    if (lane < C) out[(size_t)warp * C + lane] = myv * rnl;
}

// ---- host helper: launch with programmatic stream serialization ----------
template <typename... Args>
static void launch_pdl(void (*kern)(Args...), dim3 grid, dim3 block,
                       Args... args) {
    cudaLaunchConfig_t cfg = {};
    cfg.gridDim = grid;
    cfg.blockDim = block;
    cfg.dynamicSmemBytes = 0;
    cfg.stream = 0;
    cudaLaunchAttribute attr[1];
    attr[0].id = cudaLaunchAttributeProgrammaticStreamSerialization;
    attr[0].val.programmaticStreamSerializationAllowed = 1;
    cfg.attrs = attr;
    cfg.numAttrs = 1;
    cudaLaunchKernelEx(&cfg, kern, args...);
}

// ---- launch ---------------------------------------------------------------
extern "C" void kernel_launch(void* const* d_in, const int* in_sizes, int n_in,
                              void* d_out, int out_size) {
    const float* feature  = (const float*)d_in[0];
    const float* clf_w    = (const float*)d_in[1];
    const float* clf_b    = (const float*)d_in[2];
    const float* supports = (const float*)d_in[3];
    const float* ent_bank = (const float*)d_in[4];
    const int*   labels   = (const int*)d_in[5];
    const int*   kptr     = (const int*)d_in[6];

    int Cc = in_sizes[2];          // 17
    int Dv = in_sizes[1] / Cc;     // 512
    int B  = in_sizes[0] / Dv;     // 4096
    int N  = in_sizes[4];          // 100000
    int R  = N + B;
    (void)n_in; (void)out_size; (void)Dv;

    float* out = (float*)d_out;

    int blk1 = (B * 32 + 255) / 256;   // 512 blocks
    k_logits<<<blk1, 256>>>(feature, clf_w, clf_b, ent_bank, labels, B, N);
    launch_pdl(k_scanA, dim3(C), dim3(256), kptr);
    launch_pdl(k_compact, dim3((R + 255) / 256), dim3(256), R);
    launch_pdl(k_selB, dim3(C), dim3(256));
    launch_pdl(k_sum, dim3(CH2, C), dim3(256), supports, feature, N);
    launch_pdl(k_gemm2, dim3(blk1), dim3(256), feature, out, B);
}